// round 7
// baseline (speedup 1.0000x reference)
#include <cuda_runtime.h>
#include <cstdint>

// Problem shape (fixed by the dataset): N=8, T=256, U=128, C=512.
#define N_DIM  8
#define T_DIM  256
#define U_DIM  128
#define U1_DIM 129
#define C_DIM  512
#define ROWS   (N_DIM * T_DIM * U1_DIM)   // 264192

// Diagonal-major scratch: cell (t,u) at [d=t+u][col=u]. PITCH=136 floats
// (544B = 34 x 16B cp.async segments per row).
#define PITCH   136
#define DIAGS   (T_DIM + U_DIM)           // 384
#define DIAG_SZ (DIAGS * PITCH)           // 52224 per sample

#define NEG     (-1.0e30f)                // finite "-inf": exp underflows to 0
#define CH      4                         // diagonals per pipeline chunk
#define NCHUNK  96                        // 384 diagonals (d = 1..384)
#define SLOTS   16                        // smem ring rows = 4 chunks in flight

static __device__ __align__(16) float g_bld[N_DIM * DIAG_SZ + 512];  // blank
static __device__ __align__(16) float g_emd[N_DIM * DIAG_SZ + 512];  // emit
static __device__ float    g_loss[N_DIM];
static __device__ unsigned g_ticket;       // zero-init; last CTA resets to 0

__device__ __forceinline__ float laddexp(float x, float y) {
    float mx = fmaxf(x, y);
    return mx + __logf(1.0f + __expf(fminf(x, y) - mx));
}

__device__ __forceinline__ void cp16(unsigned int sdst, const void* gsrc) {
    asm volatile("cp.async.cg.shared.global [%0], [%1], 16;\n"
                 :: "r"(sdst), "l"(gsrc));
}
__device__ __forceinline__ void cp_commit() {
    asm volatile("cp.async.commit_group;\n" ::: "memory");
}
__device__ __forceinline__ void cp_wait3() {
    asm volatile("cp.async.wait_group 3;\n" ::: "memory");
}

// ---------------------------------------------------------------------------
// Kernel 0: flood scratch with NEG so unwritten pad slots act as -inf;
// edge cells in the wavefront then need no branches (dead path adds NEG,
// exp()==0, single-path result exactly).
// ---------------------------------------------------------------------------
__global__ void fill_kernel() {
    const int n4 = (N_DIM * DIAG_SZ + 512) / 4;
    float4 v = make_float4(NEG, NEG, NEG, NEG);
    float4* b = reinterpret_cast<float4*>(g_bld);
    float4* e = reinterpret_cast<float4*>(g_emd);
    for (int i = blockIdx.x * blockDim.x + threadIdx.x; i < n4;
         i += gridDim.x * blockDim.x) {
        b[i] = v;
        e[i] = v;
    }
}

// ---------------------------------------------------------------------------
// Kernel 1: per-row logsumexp over C=512; write blank/emit log-probs into
// diagonal-major scratch. One warp per row, 4x float4 per lane. HBM-bound
// (541 MB stream, measured at the DRAM ceiling).
// ---------------------------------------------------------------------------
__global__ void __launch_bounds__(256) lse_kernel(const float* __restrict__ act,
                                                  const int*   __restrict__ tgt) {
    int gw   = (blockIdx.x * 256 + threadIdx.x) >> 5;   // global warp = row id
    int lane = threadIdx.x & 31;
    if (gw >= ROWS) return;

    const float4* p4 = reinterpret_cast<const float4*>(act) + (size_t)gw * (C_DIM / 4);
    float4 a = p4[lane];
    float4 b = p4[lane + 32];
    float4 c = p4[lane + 64];
    float4 d = p4[lane + 96];

    float m = fmaxf(fmaxf(fmaxf(a.x, a.y), fmaxf(a.z, a.w)),
                    fmaxf(fmaxf(b.x, b.y), fmaxf(b.z, b.w)));
    m = fmaxf(m, fmaxf(fmaxf(fmaxf(c.x, c.y), fmaxf(c.z, c.w)),
                       fmaxf(fmaxf(d.x, d.y), fmaxf(d.z, d.w))));
#pragma unroll
    for (int o = 16; o; o >>= 1)
        m = fmaxf(m, __shfl_xor_sync(0xffffffffu, m, o));

    float s = __expf(a.x - m) + __expf(a.y - m) + __expf(a.z - m) + __expf(a.w - m);
    s += __expf(b.x - m) + __expf(b.y - m) + __expf(b.z - m) + __expf(b.w - m);
    s += __expf(c.x - m) + __expf(c.y - m) + __expf(c.z - m) + __expf(c.w - m);
    s += __expf(d.x - m) + __expf(d.y - m) + __expf(d.z - m) + __expf(d.w - m);
#pragma unroll
    for (int o = 16; o; o >>= 1)
        s += __shfl_xor_sync(0xffffffffu, s, o);

    if (lane == 0) {
        float lse = m + __logf(s);
        int n   = gw / (T_DIM * U1_DIM);
        int rem = gw % (T_DIM * U1_DIM);
        int t   = rem / U1_DIM;
        int u   = rem % U1_DIM;
        size_t db = (size_t)n * DIAG_SZ + (size_t)(t + u) * PITCH + u;
        g_bld[db] = a.x - lse;                 // lane 0's a.x == act[row, BLANK=0]
        if (u < U_DIM) {
            int tv = __ldg(tgt + n * U_DIM + u);
            g_emd[db] = __ldg(act + (size_t)gw * C_DIM + tv) - lse;  // L1-hot
        }
    }
}

// ---------------------------------------------------------------------------
// Kernel 2: alpha wavefront, ONE WARP per sample, register-resident state,
// cp.async smem pipeline for operands (16-row ring = 4 chunks in flight,
// fully hiding L2 latency; one wait_group+syncwarp per 4 diagonals).
//   cell (t,u), d=t+u:  alpha = laddexp(alpha[t-1][u] + bl@[d-1][u],
//                                       alpha[t][u-1] + em@[d-1][u-1])
// Lane L owns u = 4L+1..4L+4; u=0 is the blank-only FADD chain a0.
// Also folds the final mean: last CTA (ticket atomic) sums g_loss -> out.
// ---------------------------------------------------------------------------
__global__ void __launch_bounds__(32, 1) alpha_kernel(const int* __restrict__ tlen,
                                                      const int* __restrict__ ulen,
                                                      float* __restrict__ out) {
    __shared__ __align__(16) float s_bl[SLOTS][PITCH];
    __shared__ __align__(16) float s_em[SLOTS][PITCH];

    int n = blockIdx.x;
    int L = threadIdx.x;
    const float* bld = g_bld + (size_t)n * DIAG_SZ;
    const float* emd = g_emd + (size_t)n * DIAG_SZ;

    int Tn = __ldg(tlen + n);
    int Un = __ldg(ulen + n);
    int dLoss = Tn - 1 + Un;

    unsigned int sbl = (unsigned int)__cvta_generic_to_shared(&s_bl[0][0]);
    unsigned int sem = (unsigned int)__cvta_generic_to_shared(&s_em[0][0]);

    // Issue one row's copies (bl+em) into ring slot (row & 15).
    auto issue_row = [&](int row) {
        unsigned int so = (unsigned int)(row & (SLOTS - 1)) * (PITCH * 4);
        const float* gb = bld + (size_t)row * PITCH;
        const float* ge = emd + (size_t)row * PITCH;
        cp16(sbl + so + 16 * L, gb + 4 * L);
        cp16(sem + so + 16 * L, ge + 4 * L);
        if (L < 2) {                                   // segments 32,33
            cp16(sbl + so + 16 * (32 + L), gb + 4 * (32 + L));
            cp16(sem + so + 16 * (32 + L), ge + 4 * (32 + L));
        }
    };

    // Prologue: chunks 0..2 (rows 0..11), one commit group per chunk.
#pragma unroll
    for (int c = 0; c < 3; ++c) {
#pragma unroll
        for (int k = 0; k < CH; ++k) issue_row(4 * c + k);
        cp_commit();
    }

    float a0 = 0.0f;                          // alpha[0][0]
    float a[4] = {NEG, NEG, NEG, NEG};

    if (dLoss == 0 && L == 0)                 // degenerate Tn=1, Un=0
        g_loss[n] = -(a0 + __ldg(bld));

    int d = 1;
    for (int c = 0; c < NCHUNK; ++c) {
        int rf = 4 * (c + 3);                 // first row of chunk c+3
        if (rf < DIAGS) {
#pragma unroll
            for (int k = 0; k < CH; ++k) issue_row(rf + k);
        }
        cp_commit();                          // commit (possibly empty) group
        cp_wait3();                           // chunk c's rows are resident
        __syncwarp();

#pragma unroll
        for (int k = 0; k < CH; ++k, ++d) {
            int s = (d - 1) & (SLOTS - 1);
            float4 bl4 = *reinterpret_cast<const float4*>(&s_bl[s][4 * L]);
            float4 em4 = *reinterpret_cast<const float4*>(&s_em[s][4 * L]);
            float  blx = s_bl[s][4 * L + 4];
            float  bl00 = s_bl[s][0];         // uniform broadcast LDS

            float nb_in = __shfl_up_sync(0xffffffffu, a[3], 1);  // aprev[4L]
            float nb    = (L == 0) ? a0 : nb_in;

            // cells u = 4L+1..4L+4 (bl col u -> bl4.yzw/blx; em col u-1 -> em4)
            float t0 = laddexp(a[0] + bl4.y, nb   + em4.x);
            float t1 = laddexp(a[1] + bl4.z, a[0] + em4.y);
            float t2 = laddexp(a[2] + bl4.w, a[1] + em4.z);
            float t3 = laddexp(a[3] + blx,   a[2] + em4.w);
            a0 += bl00;                        // u=0 blank-only chain
            a[0] = t0; a[1] = t1; a[2] = t2; a[3] = t3;

            if (d == dLoss) {                  // warp-uniform, true once
                float fin = __ldg(bld + (size_t)dLoss * PITCH + Un);
                if (Un == 0) {
                    if (L == 0) g_loss[n] = -(a0 + fin);
                } else {
                    int tl = (Un - 1) >> 2, j = (Un - 1) & 3;
                    float v = (j == 0) ? t0 : (j == 1) ? t1 : (j == 2) ? t2 : t3;
                    float lv = __shfl_sync(0xffffffffu, v, tl);
                    if (L == 0) g_loss[n] = -(lv + fin);
                }
            }
        }
    }

    // Fold the mean: last CTA to arrive sums all losses in fixed order.
    __syncwarp();
    __threadfence();
    if (L == 0) {
        unsigned t = atomicAdd(&g_ticket, 1u);
        if (t == N_DIM - 1) {
            __threadfence();
            float s = 0.0f;
#pragma unroll
            for (int i = 0; i < N_DIM; ++i) s += g_loss[i];
            out[0] = s / (float)N_DIM;
            g_ticket = 0;                      // reset for next graph replay
        }
    }
}

extern "C" void kernel_launch(void* const* d_in, const int* in_sizes, int n_in,
                              void* d_out, int out_size) {
    const float* act  = (const float*)d_in[0];
    const int*   tgt  = (const int*)  d_in[1];
    const int*   tlen = (const int*)  d_in[2];
    const int*   ulen = (const int*)  d_in[3];
    float*       out  = (float*)      d_out;

    fill_kernel<<<400, 256>>>();
    int blocks = (ROWS + 7) / 8;              // one warp per row, 8 warps/block
    lse_kernel<<<blocks, 256>>>(act, tgt);
    alpha_kernel<<<N_DIM, 32>>>(tlen, ulen, out);
}